// round 7
// baseline (speedup 1.0000x reference)
#include <cuda_runtime.h>
#include <cuda_bf16.h>

// relu(segment_sum(x @ W^T + b))  ==  relu(segment_sum(x) @ W^T + count * b)
// N=500000, H=256, B=1024, seg_ids sorted ascending.

#define H 256
#define HV 64                  // H / 4 (float4 columns)
#define B 1024
#define TARGET_GRID 1184       // segsum: 148 SMs * 8 blocks ceiling
#define RPI 32                 // segsum rows per iteration
#define JT 8                   // finish: j tiles (32 outputs each)
#define ST 32                  // finish: segment tiles (32 segs each)
#define JW 32                  // j per tile
#define SW_PITCH 65            // row pitch in float4 (64 + 1 pad)
#define FIN_THREADS 512

__device__ float g_pooled[B * H];        // segment sums of x (zero-init)
__device__ float g_count[B];             // nodes per segment  (zero-init)
__device__ unsigned int g_done[ST];      // per-seg-tile arrival counters

// ---------------------------------------------------------------------------
// Kernel 1: segment-sum of x.  (~74us = ~6.9 TB/s -- at HBM roofline)
// ---------------------------------------------------------------------------
__device__ __forceinline__ void flush_acc(float4& acc, int cur, int c) {
    float* dst = &g_pooled[cur * H + c * 4];
    atomicAdd(dst + 0, acc.x);
    atomicAdd(dst + 1, acc.y);
    atomicAdd(dst + 2, acc.z);
    atomicAdd(dst + 3, acc.w);
    acc = make_float4(0.f, 0.f, 0.f, 0.f);
}

__global__ void __launch_bounds__(H) segsum_kernel(
    const float* __restrict__ x, const int* __restrict__ seg,
    int N, int rows_per_block)
{
    int r0 = blockIdx.x * rows_per_block;
    int r1 = min(r0 + rows_per_block, N);
    if (r0 >= r1) return;

    const int tid    = threadIdx.x;
    const int c      = tid & 63;
    const int rowoff = tid >> 6;
    const float4* __restrict__ x4 = reinterpret_cast<const float4*>(x);

    float4 acc = make_float4(0.f, 0.f, 0.f, 0.f);
    int cur       = __ldg(&seg[r0]);
    int run_start = r0;

    int r = r0;
    for (; r + RPI <= r1; r += RPI) {
        size_t base = (size_t)(r + rowoff) * HV + c;
        float4 v0 = __ldg(&x4[base + 0 * 4 * HV]);
        float4 v1 = __ldg(&x4[base + 1 * 4 * HV]);
        float4 v2 = __ldg(&x4[base + 2 * 4 * HV]);
        float4 v3 = __ldg(&x4[base + 3 * 4 * HV]);
        float4 v4 = __ldg(&x4[base + 4 * 4 * HV]);
        float4 v5 = __ldg(&x4[base + 5 * 4 * HV]);
        float4 v6 = __ldg(&x4[base + 6 * 4 * HV]);
        float4 v7 = __ldg(&x4[base + 7 * 4 * HV]);
        int s_last = __ldg(&seg[r + RPI - 1]);

        if (s_last == cur) {
            acc.x += ((v0.x + v1.x) + (v2.x + v3.x)) + ((v4.x + v5.x) + (v6.x + v7.x));
            acc.y += ((v0.y + v1.y) + (v2.y + v3.y)) + ((v4.y + v5.y) + (v6.y + v7.y));
            acc.z += ((v0.z + v1.z) + (v2.z + v3.z)) + ((v4.z + v5.z) + (v6.z + v7.z));
            acc.w += ((v0.w + v1.w) + (v2.w + v3.w)) + ((v4.w + v5.w) + (v6.w + v7.w));
        } else {
            float4 vv[8] = {v0, v1, v2, v3, v4, v5, v6, v7};
            #pragma unroll
            for (int k = 0; k < RPI; ++k) {
                int rr = r + k;
                int s = __ldg(&seg[rr]);
                if (s != cur) {
                    flush_acc(acc, cur, c);
                    if (tid == 0)
                        atomicAdd(&g_count[cur], (float)(rr - run_start));
                    cur = s; run_start = rr;
                }
                if ((k & 3) == rowoff) {
                    float4 v = vv[k >> 2];
                    acc.x += v.x; acc.y += v.y; acc.z += v.z; acc.w += v.w;
                }
            }
        }
    }
    for (; r < r1; ++r) {
        int s = __ldg(&seg[r]);
        if (s != cur) {
            flush_acc(acc, cur, c);
            if (tid == 0) atomicAdd(&g_count[cur], (float)(r - run_start));
            cur = s; run_start = r;
        }
        if (rowoff == 0) {
            float4 v = __ldg(&x4[(size_t)r * HV + c]);
            acc.x += v.x; acc.y += v.y; acc.z += v.z; acc.w += v.w;
        }
    }
    flush_acc(acc, cur, c);
    if (tid == 0) atomicAdd(&g_count[cur], (float)(r1 - run_start));
}

// ---------------------------------------------------------------------------
// Kernel 2: tiled epilogue GEMM, ROW-MAJOR smem W (no transpose).
// Block (jt, st): out[g0..g0+32)[j0..j0+32), 512 threads.
// Staging: straight float4 copy of the 32-row W tile (coalesced LDG,
// STS.128 at the 4-wavefront floor -- the previous transpose staging had
// 16-way STS bank conflicts and was L1-bound at 56%).
// Compute: thread = (j = t&31, seg pair = t>>5). Warp spans all 32 j:
//   per k4: 1 LDS.128 of own W row (4-wf floor), 2 broadcast LDGs of
//   pooled (uniform address), 8 FFMA. All pipes balance at ~the FFMA floor.
// Last of the 8 j-tile blocks per seg-tile re-zeros that scratch region.
// ---------------------------------------------------------------------------
__global__ void __launch_bounds__(FIN_THREADS) finish_kernel(
    const float* __restrict__ W, const float* __restrict__ bias,
    float* __restrict__ out)
{
    const int jt = blockIdx.x & (JT - 1);
    const int st = blockIdx.x >> 3;
    const int j0 = jt * JW;
    const int g0 = st * 32;
    const int t  = threadIdx.x;

    __shared__ __align__(16) float4 sw4[JW * SW_PITCH];   // 33.3KB row-major
    __shared__ int s_last_flag;

    // ---- stage W[j0..j0+32)[0..256) as-is: sw4[jj*65 + k4] = Wrow(jj)[k4]
    {
        const int jj = t >> 4;          // 0..31
        const int kb = t & 15;          // 0..15
        const float4* wr = reinterpret_cast<const float4*>(W + (size_t)(j0 + jj) * H);
        #pragma unroll
        for (int kc = 0; kc < 4; ++kc) {
            int k4 = kb + kc * 16;
            sw4[jj * SW_PITCH + k4] = __ldg(&wr[k4]);
        }
    }
    __syncthreads();

    // ---- compute: thread owns j = j0 + (t&31), two segments ----
    const int jl = t & 31;
    const int sp = t >> 5;              // 0..15
    const int ga = g0 + sp * 2;
    const int gb = ga + 1;

    const float4* pa4 = reinterpret_cast<const float4*>(g_pooled) + (size_t)ga * HV;
    const float4* pb4 = reinterpret_cast<const float4*>(g_pooled) + (size_t)gb * HV;
    const float4* wrow = &sw4[jl * SW_PITCH];

    const float bj  = __ldg(&bias[j0 + jl]);
    float acca = __ldg(&g_count[ga]) * bj;
    float accb = __ldg(&g_count[gb]) * bj;

    #pragma unroll 4
    for (int k4 = 0; k4 < HV; ++k4) {
        float4 w = wrow[k4];
        float4 pa = __ldg(&pa4[k4]);
        float4 pb = __ldg(&pb4[k4]);
        acca += w.x * pa.x + w.y * pa.y + w.z * pa.z + w.w * pa.w;
        accb += w.x * pb.x + w.y * pb.y + w.z * pb.z + w.w * pb.w;
    }

    out[(size_t)ga * H + j0 + jl] = fmaxf(acca, 0.f);
    out[(size_t)gb * H + j0 + jl] = fmaxf(accb, 0.f);

    // ---- last j-tile block for this seg-tile re-zeros the scratch region
    __syncthreads();           // all pooled reads complete (consumed)
    if (t == 0) {
        __threadfence();
        s_last_flag = (atomicAdd(&g_done[st], 1u) == JT - 1) ? 1 : 0;
    }
    __syncthreads();
    if (s_last_flag) {
        float4 z = make_float4(0.f, 0.f, 0.f, 0.f);
        float4* pz = reinterpret_cast<float4*>(g_pooled) + (size_t)g0 * HV;
        for (int i = t; i < 32 * HV; i += FIN_THREADS) pz[i] = z;
        if (t < 32) g_count[g0 + t] = 0.f;
        if (t == 0) g_done[st] = 0u;
    }
}

// ---------------------------------------------------------------------------
// Launch
// ---------------------------------------------------------------------------
extern "C" void kernel_launch(void* const* d_in, const int* in_sizes, int n_in,
                              void* d_out, int out_size)
{
    const float* x   = (const float*)d_in[0];   // [N, 256]
    const int*   seg = (const int*)  d_in[1];   // [N]
    const float* W   = (const float*)d_in[2];   // [256, 256]
    const float* b   = (const float*)d_in[3];   // [256]
    float* out = (float*)d_out;                 // [1024, 256]

    const int N = in_sizes[0] / H;

    int rpb = (N + TARGET_GRID - 1) / TARGET_GRID;
    rpb = ((rpb + RPI - 1) / RPI) * RPI;        // N=500000 -> 448
    int grid = (N + rpb - 1) / rpb;             // -> 1117 (single wave)

    segsum_kernel<<<grid, H>>>(x, seg, N, rpb);
    finish_kernel<<<JT * ST, FIN_THREADS>>>(W, b, out);
}